// round 6
// baseline (speedup 1.0000x reference)
#include <cuda_runtime.h>
#include <math.h>

#define Bb 64
#define Hh 512
#define Gg 2048
#define Vv 32000
#define Tt 24

// -------- scratch (static device globals; no allocation) --------
__device__ float g_hbuf[2][Bb*Hh];   // ping-pong hidden state
__device__ float g_c[Bb*Hh];
__device__ float g_xv[Gg];
__device__ unsigned long long g_amax[Tt*Bb];  // per-step argmax keys
__device__ float g_mask[Bb];
__device__ int   g_x0nz;             // x0 nonzero flag

__device__ __forceinline__ unsigned int fkey(float f){
    unsigned int u = __float_as_uint(f);
    return (u & 0x80000000u) ? ~u : (u | 0x80000000u);
}
__device__ __forceinline__ int dekey(unsigned long long key){
    return (int)(0xFFFFFFFFu - (unsigned int)(key & 0xFFFFFFFFull));
}

// -------- init: copy state, set mask=1, zero per-step amax --------
__global__ void k_init(const float* __restrict__ eh, const float* __restrict__ ec){
    int i = blockIdx.x*blockDim.x + threadIdx.x;
    if (i < Bb*Hh){ g_hbuf[0][i] = eh[i]; g_c[i] = ec[i]; }
    if (i < Bb) g_mask[i] = 1.0f;
    if (i < Tt*Bb) g_amax[i] = 0ull;
    if (i == 0) g_x0nz = 0;
}

// -------- x0 zero scan (128 KB read) --------
__global__ void k_zchk(const float* __restrict__ x0){
    int i = blockIdx.x*blockDim.x + threadIdx.x;
    int nz = 0;
    for (int v = i*4; v < Vv; v += 32768){
        float4 x = *(const float4*)(x0 + v);
        if (x.x != 0.f || x.y != 0.f || x.z != 0.f || x.w != 0.f) nz = 1;
    }
    if (__syncthreads_or(nz)) { if (threadIdx.x == 0) g_x0nz = 1; }
}

// -------- xv[j] = dot(W_ih[j,:], x0) -- early-exit when x0 == 0 --------
__global__ void k_xv(const float* __restrict__ W_ih, const float* __restrict__ x0){
    int j = blockIdx.x;
    if (!g_x0nz){ if (threadIdx.x == 0) g_xv[j] = 0.f; return; }
    const float* row = W_ih + (size_t)j*Vv;
    float s = 0.f;
    for (int v = threadIdx.x; v < Vv; v += 256) s += row[v]*x0[v];
    __shared__ float red[256];
    red[threadIdx.x] = s; __syncthreads();
    for (int o = 128; o > 0; o >>= 1){
        if (threadIdx.x < o) red[threadIdx.x] += red[threadIdx.x+o];
        __syncthreads();
    }
    if (threadIdx.x == 0) g_xv[j] = red[0];
}

// -------- fused gates GEMM + LSTM (+ step t-1 finalize in block 0) --------
// grid 128 = 32 h-tiles x 4 b-tiles. Block: 16 h (=> 64 W_hh rows) x 16 b.
__global__ void __launch_bounds__(256) k_gates(
    const float* __restrict__ W_hh, const float* __restrict__ b_ih,
    const float* __restrict__ b_hh, const float* __restrict__ W_ih,
    float* __restrict__ out, int t)
{
    __shared__ float sW[32*64];
    __shared__ float sH[32*20];
    __shared__ float sG[64*17];
    int tx = threadIdx.x;
    int ht = blockIdx.x >> 2, bt = blockIdx.x & 3;
    const float* hin  = g_hbuf[t & 1];
    float*       hout = g_hbuf[(t + 1) & 1];

    if (t > 0 && blockIdx.x == 0 && tx < Bb){
        unsigned long long key = g_amax[(t-1)*Bb + tx];
        int idx = dekey(key);
        out[(size_t)(t-1)*Bb*Vv + (size_t)tx*Vv + idx] = 1.0f;  // predicts one-hot
        out[98304000ull + (size_t)(t-1)*Bb + tx] = g_mask[tx];  // masks (pre-update)
        if (idx == 0) g_mask[tx] = 0.f;
    }

    int r = tx >> 2, bq = tx & 3;
    int gate = r >> 4, h_l = r & 15;
    int j = gate*512 + ht*16 + h_l;
    float bias = b_ih[j] + b_hh[j];
    float xterm[4];
    if (t == 0){
        float xv = g_xv[j];
        #pragma unroll
        for (int i = 0; i < 4; i++) xterm[i] = xv;
    } else {
        #pragma unroll
        for (int i = 0; i < 4; i++){
            int b = bt*16 + bq*4 + i;
            int idx = dekey(g_amax[(t-1)*Bb + b]);
            xterm[i] = W_ih[(size_t)j*Vv + idx];
        }
    }

    float acc[4] = {0.f,0.f,0.f,0.f};
    for (int k0 = 0; k0 < Hh; k0 += 32){
        __syncthreads();
        #pragma unroll
        for (int s = 0; s < 2; s++){
            int e = tx*2 + s;
            int row = e >> 3, kq = e & 7;
            int jr = (row >> 4)*512 + ht*16 + (row & 15);
            float4 w = *(const float4*)(W_hh + (size_t)jr*Hh + k0 + kq*4);
            sW[(kq*4+0)*64+row] = w.x;
            sW[(kq*4+1)*64+row] = w.y;
            sW[(kq*4+2)*64+row] = w.z;
            sW[(kq*4+3)*64+row] = w.w;
        }
        if (tx < 128){
            int lb = tx >> 3, kq = tx & 7;
            float4 hv = *(const float4*)(hin + (bt*16+lb)*Hh + k0 + kq*4);
            sH[(kq*4+0)*20+lb] = hv.x;
            sH[(kq*4+1)*20+lb] = hv.y;
            sH[(kq*4+2)*20+lb] = hv.z;
            sH[(kq*4+3)*20+lb] = hv.w;
        }
        __syncthreads();
        #pragma unroll
        for (int k = 0; k < 32; k++){
            float w = sW[k*64 + r];
            float4 h4 = *(const float4*)(sH + k*20 + bq*4);
            acc[0] = fmaf(w, h4.x, acc[0]);
            acc[1] = fmaf(w, h4.y, acc[1]);
            acc[2] = fmaf(w, h4.z, acc[2]);
            acc[3] = fmaf(w, h4.w, acc[3]);
        }
    }
    #pragma unroll
    for (int i = 0; i < 4; i++) sG[r*17 + bq*4 + i] = acc[i] + bias + xterm[i];
    __syncthreads();

    int h2 = tx & 15, b2 = tx >> 4;
    float gi = sG[( 0 + h2)*17 + b2];
    float gf = sG[(16 + h2)*17 + b2];
    float gg = sG[(32 + h2)*17 + b2];
    float go = sG[(48 + h2)*17 + b2];
    int b = bt*16 + b2, h = ht*16 + h2;
    float c  = g_c[b*Hh + h];
    float si = 1.f/(1.f+expf(-gi));
    float sf = 1.f/(1.f+expf(-gf));
    float so = 1.f/(1.f+expf(-go));
    float cn = sf*c + si*tanhf(gg);
    float hn = so*tanhf(cn);
    g_c[b*Hh + h] = cn;
    hout[b*Hh + h] = hn;
}

// -------- logits GEMM + argmax partials + output writes --------
// grid 1000 blocks (32 v each), 64 threads; thread tile: 8 v x 4 b.
// tv = tx&3 (4 v-threads x 8v), tb = tx>>2 (16 b-threads x 4b).
// 1.5 smem B/FMA, ~3 wavefronts per 32 warp-FMA-instr -> FMA-bound.
__global__ void __launch_bounds__(64) k_logits(
    const float* __restrict__ W_out, const float* __restrict__ b_out,
    float* __restrict__ out, int t)
{
    __shared__ float sW[16*32];
    __shared__ float sH[16*64];
    __shared__ unsigned long long skey[64];
    int tx = threadIdx.x;
    int vblk = blockIdx.x * 32;
    int tv = tx & 3, tb = tx >> 2;
    skey[tx] = 0ull;
    const float* hin = g_hbuf[(t + 1) & 1];

    float acc[4][8];
    #pragma unroll
    for (int i = 0; i < 4; i++)
        #pragma unroll
        for (int j = 0; j < 8; j++) acc[i][j] = 0.f;

    // loaders: W: lv = tx>>1 (32 v-rows), half = tx&1 (8 k each). H: lb = tx (64 b-rows)
    int lv = tx >> 1, half = tx & 1;
    const float* wp = W_out + (size_t)(vblk + lv)*Hh + half*8;
    const float* hp = hin + tx*Hh;
    float4 wpre0 = *(const float4*)(wp);
    float4 wpre1 = *(const float4*)(wp + 4);
    float4 hpre0 = *(const float4*)(hp);
    float4 hpre1 = *(const float4*)(hp + 4);
    float4 hpre2 = *(const float4*)(hp + 8);
    float4 hpre3 = *(const float4*)(hp + 12);

    for (int k0 = 0; k0 < Hh; k0 += 16){
        __syncthreads();
        int kb = half*8;
        sW[(kb+0)*32+lv] = wpre0.x; sW[(kb+1)*32+lv] = wpre0.y;
        sW[(kb+2)*32+lv] = wpre0.z; sW[(kb+3)*32+lv] = wpre0.w;
        sW[(kb+4)*32+lv] = wpre1.x; sW[(kb+5)*32+lv] = wpre1.y;
        sW[(kb+6)*32+lv] = wpre1.z; sW[(kb+7)*32+lv] = wpre1.w;
        sH[ 0*64+tx] = hpre0.x; sH[ 1*64+tx] = hpre0.y;
        sH[ 2*64+tx] = hpre0.z; sH[ 3*64+tx] = hpre0.w;
        sH[ 4*64+tx] = hpre1.x; sH[ 5*64+tx] = hpre1.y;
        sH[ 6*64+tx] = hpre1.z; sH[ 7*64+tx] = hpre1.w;
        sH[ 8*64+tx] = hpre2.x; sH[ 9*64+tx] = hpre2.y;
        sH[10*64+tx] = hpre2.z; sH[11*64+tx] = hpre2.w;
        sH[12*64+tx] = hpre3.x; sH[13*64+tx] = hpre3.y;
        sH[14*64+tx] = hpre3.z; sH[15*64+tx] = hpre3.w;
        __syncthreads();
        if (k0 + 16 < Hh){
            wpre0 = *(const float4*)(wp + k0 + 16);
            wpre1 = *(const float4*)(wp + k0 + 20);
            hpre0 = *(const float4*)(hp + k0 + 16);
            hpre1 = *(const float4*)(hp + k0 + 20);
            hpre2 = *(const float4*)(hp + k0 + 24);
            hpre3 = *(const float4*)(hp + k0 + 28);
        }
        #pragma unroll
        for (int k = 0; k < 16; k++){
            float4 wa = *(const float4*)(sW + k*32 + tv*8);
            float4 wb = *(const float4*)(sW + k*32 + tv*8 + 4);
            float4 h4 = *(const float4*)(sH + k*64 + tb*4);
            float hv[4] = {h4.x, h4.y, h4.z, h4.w};
            float wv[8] = {wa.x, wa.y, wa.z, wa.w, wb.x, wb.y, wb.z, wb.w};
            #pragma unroll
            for (int i = 0; i < 4; i++)
                #pragma unroll
                for (int j = 0; j < 8; j++)
                    acc[i][j] = fmaf(hv[i], wv[j], acc[i][j]);
        }
    }

    // epilogue: bias, vectorized logits + predicts-zero stores, argmax partials
    size_t base = (size_t)t * Bb * Vv;
    float* logits = out + 49152000ull;   // T*B*V
    int v0 = vblk + tv*8;
    float4 bo0 = *(const float4*)(b_out + v0);
    float4 bo1 = *(const float4*)(b_out + v0 + 4);
    float4 zero4 = make_float4(0.f, 0.f, 0.f, 0.f);
    #pragma unroll
    for (int i = 0; i < 4; i++){
        int b = tb*4 + i;
        float4 r0, r1;
        r0.x = acc[i][0] + bo0.x; r0.y = acc[i][1] + bo0.y;
        r0.z = acc[i][2] + bo0.z; r0.w = acc[i][3] + bo0.w;
        r1.x = acc[i][4] + bo1.x; r1.y = acc[i][5] + bo1.y;
        r1.z = acc[i][6] + bo1.z; r1.w = acc[i][7] + bo1.w;
        size_t o = base + (size_t)b*Vv + v0;
        *(float4*)(logits + o)     = r0;
        *(float4*)(logits + o + 4) = r1;
        *(float4*)(out + o)     = zero4;   // predicts zero-fill
        *(float4*)(out + o + 4) = zero4;
        float vals[8] = {r0.x,r0.y,r0.z,r0.w,r1.x,r1.y,r1.z,r1.w};
        unsigned long long best = 0ull;
        #pragma unroll
        for (int j = 0; j < 8; j++){
            unsigned long long key =
                ((unsigned long long)fkey(vals[j]) << 32) |
                (unsigned long long)(0xFFFFFFFFu - (unsigned)(v0 + j));
            if (key > best) best = key;
        }
        atomicMax(&skey[b], best);
    }
    __syncthreads();
    if (skey[tx]) atomicMax(&g_amax[(size_t)t*Bb + tx], skey[tx]);
}

// -------- trailing finalize for the last step --------
__global__ void k_final(float* __restrict__ out){
    int b = threadIdx.x;
    if (b >= Bb) return;
    unsigned long long key = g_amax[(Tt-1)*Bb + b];
    int idx = dekey(key);
    out[(size_t)(Tt-1)*Bb*Vv + (size_t)b*Vv + idx] = 1.0f;
    out[98304000ull + (size_t)(Tt-1)*Bb + b] = g_mask[b];
}

extern "C" void kernel_launch(void* const* d_in, const int* in_sizes, int n_in,
                              void* d_out, int out_size){
    const float* eh    = (const float*)d_in[0];
    const float* ec    = (const float*)d_in[1];
    const float* W_ih  = (const float*)d_in[2];
    const float* W_hh  = (const float*)d_in[3];
    const float* b_ih  = (const float*)d_in[4];
    const float* b_hh  = (const float*)d_in[5];
    const float* W_out = (const float*)d_in[6];
    const float* b_out = (const float*)d_in[7];
    const float* x0    = (const float*)d_in[8];
    float* out = (float*)d_out;

    k_init<<<128, 256>>>(eh, ec);
    k_zchk<<<8, 1024>>>(x0);
    k_xv<<<Gg, 256>>>(W_ih, x0);
    for (int t = 0; t < Tt; t++){
        k_gates<<<128, 256>>>(W_hh, b_ih, b_hh, W_ih, out, t);
        k_logits<<<1000, 64>>>(W_out, b_out, out, t);
    }
    k_final<<<1, 64>>>(out);
}

// round 9
// speedup vs baseline: 1.3072x; 1.3072x over previous
#include <cuda_runtime.h>
#include <cstdint>
#include <stdint.h>
#include <math.h>

#define Bb 64
#define Hh 512
#define Gg 2048
#define Vv 32000
#define Tt 24

// -------- scratch (static device globals; no allocation) --------
__device__ float g_WoutT[Hh*Vv];      // W_out transposed [k][v]  (65.5 MB)
__device__ float g_WhhT[Hh*Gg];       // W_hh transposed [k][j]   (4 MB)
__device__ float g_hT[2][Hh*Bb];      // hidden state transposed [k][b], ping-pong
__device__ float g_c[Bb*Hh];
__device__ float g_xv[Gg];
__device__ unsigned long long g_amax[Tt*Bb];
__device__ float g_mask[Bb];
__device__ int   g_x0nz;

__device__ __forceinline__ unsigned int fkey(float f){
    unsigned int u = __float_as_uint(f);
    return (u & 0x80000000u) ? ~u : (u | 0x80000000u);
}
__device__ __forceinline__ int dekey(unsigned long long key){
    return (int)(0xFFFFFFFFu - (unsigned int)(key & 0xFFFFFFFFull));
}
__device__ __forceinline__ void cp16(unsigned int smem_dst, const float* gsrc){
    asm volatile("cp.async.cg.shared.global [%0], [%1], 16;" :: "r"(smem_dst), "l"(gsrc));
}
#define CP_COMMIT() asm volatile("cp.async.commit_group;")
#define CP_WAIT1()  asm volatile("cp.async.wait_group 1;")

// -------- init: copy state (h transposed), set mask --------
__global__ void k_init(const float* __restrict__ eh, const float* __restrict__ ec){
    int i = blockIdx.x*blockDim.x + threadIdx.x;
    if (i < Bb*Hh){
        int b = i >> 9, k = i & 511;
        g_hT[0][k*Bb + b] = eh[i];
        g_c[i] = ec[i];
    }
    if (i < Bb) g_mask[i] = 1.0f;
    if (i < Tt*Bb) g_amax[i] = 0ull;
    if (i == 0) g_x0nz = 0;
}

// -------- tiled transpose: dst[k][v] = src[v][k]; src is [rows][cols] --------
__global__ void k_transpose(const float* __restrict__ src, float* __restrict__ dst,
                            int rows, int cols){
    __shared__ float tile[32][33];
    int c0 = blockIdx.y * 32;       // col (k) tile
    int r0 = blockIdx.x * 32;       // row (v) tile
    int x = threadIdx.x, y0 = threadIdx.y;
    #pragma unroll
    for (int y = y0; y < 32; y += 8)
        tile[y][x] = src[(size_t)(r0 + y)*cols + c0 + x];
    __syncthreads();
    #pragma unroll
    for (int y = y0; y < 32; y += 8)
        dst[(size_t)(c0 + y)*rows + r0 + x] = tile[x][y];
}

// -------- x0 zero scan --------
__global__ void k_zchk(const float* __restrict__ x0){
    int i = blockIdx.x*blockDim.x + threadIdx.x;
    int nz = 0;
    for (int v = i*4; v < Vv; v += 32768){
        float4 x = *(const float4*)(x0 + v);
        if (x.x != 0.f || x.y != 0.f || x.z != 0.f || x.w != 0.f) nz = 1;
    }
    if (__syncthreads_or(nz)) { if (threadIdx.x == 0) g_x0nz = 1; }
}

// -------- xv[j] = dot(W_ih[j,:], x0) -- early-exit when x0 == 0 --------
__global__ void k_xv(const float* __restrict__ W_ih, const float* __restrict__ x0){
    int j = blockIdx.x;
    if (!g_x0nz){ if (threadIdx.x == 0) g_xv[j] = 0.f; return; }
    const float* row = W_ih + (size_t)j*Vv;
    float s = 0.f;
    for (int v = threadIdx.x; v < Vv; v += 256) s += row[v]*x0[v];
    __shared__ float red[256];
    red[threadIdx.x] = s; __syncthreads();
    for (int o = 128; o > 0; o >>= 1){
        if (threadIdx.x < o) red[threadIdx.x] += red[threadIdx.x+o];
        __syncthreads();
    }
    if (threadIdx.x == 0) g_xv[j] = red[0];
}

// -------- fused gates GEMM + LSTM (+ step t-1 finalize in block 0) --------
// grid 128 = 32 ht x 4 bt. Block: 64 W-rows (16 h x 4 gates) x 16 b.
// cp.async double-buffered k-tiles of 32 from transposed weights/state.
__global__ void __launch_bounds__(256) k_gates(
    const float* __restrict__ b_ih, const float* __restrict__ b_hh,
    const float* __restrict__ W_ih, float* __restrict__ out, int t)
{
    __shared__ float sW[2][32*64];
    __shared__ float sH[2][32*16];
    __shared__ float sG[64*17];
    int tx = threadIdx.x;
    int ht = blockIdx.x >> 2, bt = blockIdx.x & 3;
    const float* hT = g_hT[t & 1];

    int r = tx >> 2, bq = tx & 3;
    int gate = r >> 4, h_l = r & 15;
    int j = gate*512 + ht*16 + h_l;

    // early xterm gather (independent DRAM loads, hidden under mainloop)
    float xterm[4];
    if (t == 0){
        float xv = g_xv[j];
        #pragma unroll
        for (int i = 0; i < 4; i++) xterm[i] = xv;
    } else {
        #pragma unroll
        for (int i = 0; i < 4; i++){
            int b = bt*16 + bq*4 + i;
            int idx = dekey(g_amax[(t-1)*Bb + b]);
            xterm[i] = __ldg(W_ih + (size_t)j*Vv + idx);
        }
    }
    float bias = b_ih[j] + b_hh[j];

    // finalize duties for step t-1
    if (t > 0 && blockIdx.x == 0 && tx < Bb){
        unsigned long long key = g_amax[(t-1)*Bb + tx];
        int idx = dekey(key);
        out[(size_t)(t-1)*Bb*Vv + (size_t)tx*Vv + idx] = 1.0f;
        out[98304000ull + (size_t)(t-1)*Bb + tx] = g_mask[tx];
        if (idx == 0) g_mask[tx] = 0.f;
    }

    // loader indices
    int wc0 = tx*2;                        // 512 W chunks: k = c>>4, jq = c&15
    unsigned int swb[2], shb[2];
    swb[0] = (unsigned int)__cvta_generic_to_shared(&sW[0][0]);
    swb[1] = (unsigned int)__cvta_generic_to_shared(&sW[1][0]);
    shb[0] = (unsigned int)__cvta_generic_to_shared(&sH[0][0]);
    shb[1] = (unsigned int)__cvta_generic_to_shared(&sH[1][0]);

    #define G_ISSUE(buf, tile) do{                                             \
        int k0_ = (tile)*32;                                                   \
        _Pragma("unroll")                                                      \
        for (int s = 0; s < 2; s++){                                           \
            int c = wc0 + s;                                                   \
            int kk = c >> 4, jq = c & 15;                                      \
            int gg_ = jq >> 2, hl_ = (jq & 3)*4;                               \
            cp16(swb[buf] + (unsigned int)(kk*64 + jq*4)*4,                    \
                 g_WhhT + (size_t)(k0_+kk)*Gg + gg_*512 + ht*16 + hl_);        \
        }                                                                      \
        if (tx < 128){                                                         \
            int kk = tx >> 2, bq_ = tx & 3;                                    \
            cp16(shb[buf] + (unsigned int)(kk*16 + bq_*4)*4,                   \
                 hT + (size_t)(k0_+kk)*Bb + bt*16 + bq_*4);                    \
        }                                                                      \
    } while(0)

    float acc[4] = {0.f,0.f,0.f,0.f};
    G_ISSUE(0, 0); CP_COMMIT();
    G_ISSUE(1, 1); CP_COMMIT();
    for (int i = 0; i < 16; i++){
        CP_WAIT1();
        __syncthreads();
        int buf = i & 1;
        #pragma unroll
        for (int k = 0; k < 32; k++){
            float w = sW[buf][k*64 + r];
            float4 h4 = *(const float4*)(&sH[buf][k*16 + bq*4]);
            acc[0] = fmaf(w, h4.x, acc[0]);
            acc[1] = fmaf(w, h4.y, acc[1]);
            acc[2] = fmaf(w, h4.z, acc[2]);
            acc[3] = fmaf(w, h4.w, acc[3]);
        }
        __syncthreads();
        if (i + 2 < 16) G_ISSUE(buf, i + 2);
        CP_COMMIT();
    }
    #undef G_ISSUE

    #pragma unroll
    for (int i = 0; i < 4; i++) sG[r*17 + bq*4 + i] = acc[i] + bias + xterm[i];
    __syncthreads();

    // LSTM elementwise; write h transposed
    int h2 = tx & 15, b2 = tx >> 4;
    float gi = sG[( 0 + h2)*17 + b2];
    float gf = sG[(16 + h2)*17 + b2];
    float gg = sG[(32 + h2)*17 + b2];
    float go = sG[(48 + h2)*17 + b2];
    int b = bt*16 + b2, h = ht*16 + h2;
    float c  = g_c[b*Hh + h];
    float si = 1.f/(1.f+expf(-gi));
    float sf = 1.f/(1.f+expf(-gf));
    float so = 1.f/(1.f+expf(-go));
    float cn = sf*c + si*tanhf(gg);
    float hn = so*tanhf(cn);
    g_c[b*Hh + h] = cn;
    g_hT[(t + 1) & 1][h*Bb + b] = hn;
}

// -------- logits GEMM + argmax partials + output writes --------
// grid 1000 blocks (32 v each), 64 threads; thread tile 8v x 4b.
// k-major smem from transposed gmem via cp.async; conflict-free LDS.
__global__ void __launch_bounds__(64) k_logits(
    const float* __restrict__ b_out, float* __restrict__ out, int t)
{
    __shared__ float sW[2][16*32];
    __shared__ float sH[2][16*64];
    __shared__ unsigned long long skey[64];
    int tx = threadIdx.x;
    int vblk = blockIdx.x * 32;
    int tv = tx & 3, tb = tx >> 2;
    skey[tx] = 0ull;
    const float* hT = g_hT[(t + 1) & 1];

    float acc[4][8];
    #pragma unroll
    for (int i = 0; i < 4; i++)
        #pragma unroll
        for (int j = 0; j < 8; j++) acc[i][j] = 0.f;

    unsigned int swb[2], shb[2];
    swb[0] = (unsigned int)__cvta_generic_to_shared(&sW[0][0]);
    swb[1] = (unsigned int)__cvta_generic_to_shared(&sW[1][0]);
    shb[0] = (unsigned int)__cvta_generic_to_shared(&sH[0][0]);
    shb[1] = (unsigned int)__cvta_generic_to_shared(&sH[1][0]);

    #define L_ISSUE(buf, tile) do{                                             \
        int k0_ = (tile)*16;                                                   \
        _Pragma("unroll")                                                      \
        for (int s = 0; s < 2; s++){           /* 128 W chunks */              \
            int c = tx*2 + s;                                                  \
            int kk = c >> 3, vq = c & 7;                                       \
            cp16(swb[buf] + (unsigned int)(kk*32 + vq*4)*4,                    \
                 g_WoutT + (size_t)(k0_+kk)*Vv + vblk + vq*4);                 \
        }                                                                      \
        _Pragma("unroll")                                                      \
        for (int s = 0; s < 4; s++){           /* 256 H chunks */              \
            int c = tx*4 + s;                                                  \
            int kk = c >> 4, bq = c & 15;                                      \
            cp16(shb[buf] + (unsigned int)(kk*64 + bq*4)*4,                    \
                 hT + (size_t)(k0_+kk)*Bb + bq*4);                             \
        }                                                                      \
    } while(0)

    L_ISSUE(0, 0); CP_COMMIT();
    L_ISSUE(1, 1); CP_COMMIT();
    for (int i = 0; i < 32; i++){
        CP_WAIT1();
        __syncthreads();
        int buf = i & 1;
        #pragma unroll
        for (int k = 0; k < 16; k++){
            float4 wa = *(const float4*)(&sW[buf][k*32 + tv*8]);
            float4 wb = *(const float4*)(&sW[buf][k*32 + tv*8 + 4]);
            float4 h4 = *(const float4*)(&sH[buf][k*64 + tb*4]);
            float hv[4] = {h4.x, h4.y, h4.z, h4.w};
            float wv[8] = {wa.x, wa.y, wa.z, wa.w, wb.x, wb.y, wb.z, wb.w};
            #pragma unroll
            for (int ii = 0; ii < 4; ii++)
                #pragma unroll
                for (int jj = 0; jj < 8; jj++)
                    acc[ii][jj] = fmaf(hv[ii], wv[jj], acc[ii][jj]);
        }
        __syncthreads();
        if (i + 2 < 32) L_ISSUE(buf, i + 2);
        CP_COMMIT();
    }
    #undef L_ISSUE

    // epilogue
    size_t base = (size_t)t * Bb * Vv;
    float* logits = out + 49152000ull;
    int v0 = vblk + tv*8;
    float4 bo0 = *(const float4*)(b_out + v0);
    float4 bo1 = *(const float4*)(b_out + v0 + 4);
    float4 zero4 = make_float4(0.f, 0.f, 0.f, 0.f);
    #pragma unroll
    for (int i = 0; i < 4; i++){
        int b = tb*4 + i;
        float4 r0, r1;
        r0.x = acc[i][0] + bo0.x; r0.y = acc[i][1] + bo0.y;
        r0.z = acc[i][2] + bo0.z; r0.w = acc[i][3] + bo0.w;
        r1.x = acc[i][4] + bo1.x; r1.y = acc[i][5] + bo1.y;
        r1.z = acc[i][6] + bo1.z; r1.w = acc[i][7] + bo1.w;
        size_t o = base + (size_t)b*Vv + v0;
        *(float4*)(logits + o)     = r0;
        *(float4*)(logits + o + 4) = r1;
        *(float4*)(out + o)     = zero4;
        *(float4*)(out + o + 4) = zero4;
        float vals[8] = {r0.x,r0.y,r0.z,r0.w,r1.x,r1.y,r1.z,r1.w};
        unsigned long long best = 0ull;
        #pragma unroll
        for (int j = 0; j < 8; j++){
            unsigned long long key =
                ((unsigned long long)fkey(vals[j]) << 32) |
                (unsigned long long)(0xFFFFFFFFu - (unsigned)(v0 + j));
            if (key > best) best = key;
        }
        atomicMax(&skey[b], best);
    }
    __syncthreads();
    if (skey[tx]) atomicMax(&g_amax[(size_t)t*Bb + tx], skey[tx]);
}

// -------- trailing finalize --------
__global__ void k_final(float* __restrict__ out){
    int b = threadIdx.x;
    if (b >= Bb) return;
    unsigned long long key = g_amax[(Tt-1)*Bb + b];
    int idx = dekey(key);
    out[(size_t)(Tt-1)*Bb*Vv + (size_t)b*Vv + idx] = 1.0f;
    out[98304000ull + (size_t)(Tt-1)*Bb + b] = g_mask[b];
}

extern "C" void kernel_launch(void* const* d_in, const int* in_sizes, int n_in,
                              void* d_out, int out_size){
    const float* eh    = (const float*)d_in[0];
    const float* ec    = (const float*)d_in[1];
    const float* W_ih  = (const float*)d_in[2];
    const float* W_hh  = (const float*)d_in[3];
    const float* b_ih  = (const float*)d_in[4];
    const float* b_hh  = (const float*)d_in[5];
    const float* W_out = (const float*)d_in[6];
    const float* b_out = (const float*)d_in[7];
    const float* x0    = (const float*)d_in[8];
    float* out = (float*)d_out;

    float* WoutT; cudaGetSymbolAddress((void**)&WoutT, g_WoutT);
    float* WhhT;  cudaGetSymbolAddress((void**)&WhhT,  g_WhhT);

    k_init<<<128, 256>>>(eh, ec);
    {   dim3 g(Vv/32, Hh/32), b(32, 8);
        k_transpose<<<g, b>>>(W_out, WoutT, Vv, Hh); }
    {   dim3 g(Gg/32, Hh/32), b(32, 8);
        k_transpose<<<g, b>>>(W_hh, WhhT, Gg, Hh); }
    k_zchk<<<8, 1024>>>(x0);
    k_xv<<<Gg, 256>>>(W_ih, x0);
    for (int t = 0; t < Tt; t++){
        k_gates<<<128, 256>>>(b_ih, b_hh, W_ih, out, t);
        k_logits<<<1000, 64>>>(b_out, out, t);
    }
    k_final<<<1, 64>>>(out);
}

// round 11
// speedup vs baseline: 1.7632x; 1.3488x over previous
#include <cuda_runtime.h>
#include <cuda_bf16.h>
#include <cstdint>
#include <stdint.h>
#include <math.h>

#define Bb 64
#define Hh 512
#define Gg 2048
#define Vv 32000
#define Tt 24

#define NVT 250                 // v tiles of 128
#define NKC 16                  // k chunks of 32
#define WSTEP 24576             // bytes per (tile,kchunk): 3 splits x 128 v x 32 k x 2B
#define HSTEP 12288             // bytes per kchunk: 3 splits x 64 b x 32 k x 2B
#define PITCH 80                // smem row pitch bytes (32 bf16 data + 8 pad)
#define WREG  30720             // 3 * 128 * 80
#define HREG  15360             // 3 * 64 * 80
#define STAGE 46080             // WREG + HREG
#define DPITCH 132              // epilogue smem pitch (floats)

// -------- scratch (static device globals; no allocation) --------
__device__ __nv_bfloat16 g_Wsplit[(size_t)NVT*NKC*(WSTEP/2)];  // 98.3 MB
__device__ __nv_bfloat16 g_Hsplit[NKC*(HSTEP/2)];              // 196 KB
__device__ float g_WhhT[Hh*Gg];
__device__ float g_hT[2][Hh*Bb];
__device__ float g_c[Bb*Hh];
__device__ float g_xv[Gg];
__device__ unsigned long long g_amax[Tt*Bb];
__device__ float g_mask[Bb];
__device__ int   g_x0nz;

__device__ __forceinline__ unsigned fkey(float f){
    unsigned u = __float_as_uint(f);
    return (u & 0x80000000u) ? ~u : (u | 0x80000000u);
}
__device__ __forceinline__ int dekey(unsigned long long key){
    return (int)(0xFFFFFFFFu - (unsigned)(key & 0xFFFFFFFFull));
}
__device__ __forceinline__ void cp16(unsigned d, const void* s){
    asm volatile("cp.async.cg.shared.global [%0], [%1], 16;" :: "r"(d), "l"(s));
}
#define CP_COMMIT() asm volatile("cp.async.commit_group;")
#define CP_WAIT1()  asm volatile("cp.async.wait_group 1;")
__device__ __forceinline__ unsigned smem_u32(const void* p){
    return (unsigned)__cvta_generic_to_shared(p);
}
__device__ __forceinline__ void mma16816(float* d, const unsigned* a, const unsigned* b){
    asm volatile(
        "mma.sync.aligned.m16n8k16.row.col.f32.bf16.bf16.f32 "
        "{%0,%1,%2,%3}, {%4,%5,%6,%7}, {%8,%9}, {%0,%1,%2,%3};"
        : "+f"(d[0]), "+f"(d[1]), "+f"(d[2]), "+f"(d[3])
        : "r"(a[0]), "r"(a[1]), "r"(a[2]), "r"(a[3]), "r"(b[0]), "r"(b[1]));
}

// -------- init --------
__global__ void k_init(const float* __restrict__ eh, const float* __restrict__ ec){
    int i = blockIdx.x*blockDim.x + threadIdx.x;
    if (i < Bb*Hh){
        int b = i >> 9, k = i & 511;
        g_hT[0][k*Bb + b] = eh[i];
        g_c[i] = ec[i];
    }
    if (i < Bb) g_mask[i] = 1.0f;
    if (i < Tt*Bb) g_amax[i] = 0ull;
    if (i == 0) g_x0nz = 0;
}

// -------- W_out 3-way bf16 split: layout [tile][kc][split][v][k32] --------
__global__ void __launch_bounds__(256) k_wsplit(const float* __restrict__ W){
    long long tid = (long long)blockIdx.x*256 + threadIdx.x;
    int v  = (int)(tid >> 6);
    int k0 = ((int)tid & 63) << 3;
    const float4* src = (const float4*)(W + (size_t)v*Hh + k0);
    float4 a = src[0], b4 = src[1];
    float w[8] = {a.x, a.y, a.z, a.w, b4.x, b4.y, b4.z, b4.w};
    unsigned p1[4], p2[4], p3[4];
    #pragma unroll
    for (int i = 0; i < 4; i++){
        unsigned lo[3], hi[3];
        #pragma unroll
        for (int half = 0; half < 2; half++){
            float x = w[2*i + half];
            __nv_bfloat16 s1 = __float2bfloat16(x);
            float r = x - __bfloat162float(s1);
            __nv_bfloat16 s2 = __float2bfloat16(r);
            float r2 = r - __bfloat162float(s2);
            __nv_bfloat16 s3 = __float2bfloat16(r2);
            unsigned* dst = half ? hi : lo;
            dst[0] = __bfloat16_as_ushort(s1);
            dst[1] = __bfloat16_as_ushort(s2);
            dst[2] = __bfloat16_as_ushort(s3);
        }
        p1[i] = lo[0] | (hi[0] << 16);
        p2[i] = lo[1] | (hi[1] << 16);
        p3[i] = lo[2] | (hi[2] << 16);
    }
    int tile = v >> 7, kc = k0 >> 5;
    char* base = (char*)g_Wsplit + ((size_t)(tile*NKC + kc)*3)*8192
               + (size_t)(v & 127)*64 + (size_t)(k0 & 31)*2;
    *(uint4*)(base        ) = make_uint4(p1[0], p1[1], p1[2], p1[3]);
    *(uint4*)(base +  8192) = make_uint4(p2[0], p2[1], p2[2], p2[3]);
    *(uint4*)(base + 16384) = make_uint4(p3[0], p3[1], p3[2], p3[3]);
}

// -------- transpose for W_hh --------
__global__ void k_transpose(const float* __restrict__ src, float* __restrict__ dst,
                            int rows, int cols){
    __shared__ float tile[32][33];
    int c0 = blockIdx.y * 32, r0 = blockIdx.x * 32;
    int x = threadIdx.x, y0 = threadIdx.y;
    #pragma unroll
    for (int y = y0; y < 32; y += 8)
        tile[y][x] = src[(size_t)(r0 + y)*cols + c0 + x];
    __syncthreads();
    #pragma unroll
    for (int y = y0; y < 32; y += 8)
        dst[(size_t)(c0 + y)*rows + r0 + x] = tile[x][y];
}

// -------- x0 zero scan --------
__global__ void k_zchk(const float* __restrict__ x0){
    int i = blockIdx.x*blockDim.x + threadIdx.x;
    int nz = 0;
    for (int v = i*4; v < Vv; v += 32768){
        float4 x = *(const float4*)(x0 + v);
        if (x.x != 0.f || x.y != 0.f || x.z != 0.f || x.w != 0.f) nz = 1;
    }
    if (__syncthreads_or(nz)) { if (threadIdx.x == 0) g_x0nz = 1; }
}

// -------- xv[j] = dot(W_ih[j,:], x0) --------
__global__ void k_xv(const float* __restrict__ W_ih, const float* __restrict__ x0){
    int j = blockIdx.x;
    if (!g_x0nz){ if (threadIdx.x == 0) g_xv[j] = 0.f; return; }
    const float* row = W_ih + (size_t)j*Vv;
    float s = 0.f;
    for (int v = threadIdx.x; v < Vv; v += 256) s += row[v]*x0[v];
    __shared__ float red[256];
    red[threadIdx.x] = s; __syncthreads();
    for (int o = 128; o > 0; o >>= 1){
        if (threadIdx.x < o) red[threadIdx.x] += red[threadIdx.x+o];
        __syncthreads();
    }
    if (threadIdx.x == 0) g_xv[j] = red[0];
}

// -------- fused gates GEMM + LSTM + h-split emit (+ t-1 finalize) --------
__global__ void __launch_bounds__(256) k_gates(
    const float* __restrict__ b_ih, const float* __restrict__ b_hh,
    const float* __restrict__ W_ih, float* __restrict__ out, int t)
{
    __shared__ float sW[2][32*64];
    __shared__ float sH[2][32*16];
    __shared__ float sG[64*17];
    int tx = threadIdx.x;
    int ht = blockIdx.x >> 2, bt = blockIdx.x & 3;
    const float* hT = g_hT[t & 1];

    int r = tx >> 2, bq = tx & 3;
    int gate = r >> 4, h_l = r & 15;
    int j = gate*512 + ht*16 + h_l;

    float xterm[4];
    if (t == 0){
        float xv = g_xv[j];
        #pragma unroll
        for (int i = 0; i < 4; i++) xterm[i] = xv;
    } else {
        #pragma unroll
        for (int i = 0; i < 4; i++){
            int b = bt*16 + bq*4 + i;
            int idx = dekey(g_amax[(t-1)*Bb + b]);
            xterm[i] = __ldg(W_ih + (size_t)j*Vv + idx);
        }
    }
    float bias = b_ih[j] + b_hh[j];

    if (t > 0 && blockIdx.x == 0 && tx < Bb){
        unsigned long long key = g_amax[(t-1)*Bb + tx];
        int idx = dekey(key);
        out[(size_t)(t-1)*Bb*Vv + (size_t)tx*Vv + idx] = 1.0f;
        out[98304000ull + (size_t)(t-1)*Bb + tx] = g_mask[tx];
        if (idx == 0) g_mask[tx] = 0.f;
    }

    int wc0 = tx*2;
    unsigned swb[2], shb[2];
    swb[0] = smem_u32(&sW[0][0]); swb[1] = smem_u32(&sW[1][0]);
    shb[0] = smem_u32(&sH[0][0]); shb[1] = smem_u32(&sH[1][0]);

    #define G_ISSUE(buf, tile) do{                                             \
        int k0_ = (tile)*32;                                                   \
        _Pragma("unroll")                                                      \
        for (int s = 0; s < 2; s++){                                           \
            int c = wc0 + s;                                                   \
            int kk = c >> 4, jq = c & 15;                                      \
            int gg_ = jq >> 2, hl_ = (jq & 3)*4;                               \
            cp16(swb[buf] + (unsigned)(kk*64 + jq*4)*4,                        \
                 g_WhhT + (size_t)(k0_+kk)*Gg + gg_*512 + ht*16 + hl_);        \
        }                                                                      \
        if (tx < 128){                                                         \
            int kk = tx >> 2, bq_ = tx & 3;                                    \
            cp16(shb[buf] + (unsigned)(kk*16 + bq_*4)*4,                       \
                 hT + (size_t)(k0_+kk)*Bb + bt*16 + bq_*4);                    \
        }                                                                      \
    } while(0)

    float acc[4] = {0.f,0.f,0.f,0.f};
    G_ISSUE(0, 0); CP_COMMIT();
    G_ISSUE(1, 1); CP_COMMIT();
    for (int i = 0; i < 16; i++){
        CP_WAIT1();
        __syncthreads();
        int buf = i & 1;
        #pragma unroll
        for (int k = 0; k < 32; k++){
            float w = sW[buf][k*64 + r];
            float4 h4 = *(const float4*)(&sH[buf][k*16 + bq*4]);
            acc[0] = fmaf(w, h4.x, acc[0]);
            acc[1] = fmaf(w, h4.y, acc[1]);
            acc[2] = fmaf(w, h4.z, acc[2]);
            acc[3] = fmaf(w, h4.w, acc[3]);
        }
        __syncthreads();
        if (i + 2 < 16) G_ISSUE(buf, i + 2);
        CP_COMMIT();
    }
    #undef G_ISSUE

    #pragma unroll
    for (int i = 0; i < 4; i++) sG[r*17 + bq*4 + i] = acc[i] + bias + xterm[i];
    __syncthreads();

    int h2 = tx & 15, b2 = tx >> 4;
    float gi = sG[( 0 + h2)*17 + b2];
    float gf = sG[(16 + h2)*17 + b2];
    float gg = sG[(32 + h2)*17 + b2];
    float go = sG[(48 + h2)*17 + b2];
    int b = bt*16 + b2, h = ht*16 + h2;
    float c  = g_c[b*Hh + h];
    float si = 1.f/(1.f+expf(-gi));
    float sf = 1.f/(1.f+expf(-gf));
    float so = 1.f/(1.f+expf(-go));
    float cn = sf*c + si*tanhf(gg);
    float hn = so*tanhf(cn);
    g_c[b*Hh + h] = cn;
    g_hT[(t + 1) & 1][h*Bb + b] = hn;

    // 3-way bf16 split of hn -> g_Hsplit[kc][split][b][k32]
    __nv_bfloat16 s1 = __float2bfloat16(hn);
    float r1 = hn - __bfloat162float(s1);
    __nv_bfloat16 s2 = __float2bfloat16(r1);
    float r2 = r1 - __bfloat162float(s2);
    __nv_bfloat16 s3 = __float2bfloat16(r2);
    int kc = h >> 5, koff = h & 31;
    size_t eb = ((size_t)(kc*3)*64 + b)*32 + koff;
    g_Hsplit[eb           ] = s1;
    g_Hsplit[eb + 64*32   ] = s2;
    g_Hsplit[eb + 2*64*32 ] = s3;
}

// -------- logits via mma.sync bf16x3 (6 split-products) --------
// grid 250, 128 thr (4 warps). Block tile 128v x 64b, warp tile 32v x 64b.
// k-chunks of 32, cp.async double-buffered. Epilogue: smem-staged coalesced
// stores + warp-reduced argmax.
__global__ void __launch_bounds__(128) k_logits_mma(
    const float* __restrict__ b_out, float* __restrict__ out, int t)
{
    extern __shared__ char dyn[];
    int tx = threadIdx.x;
    int vt = blockIdx.x;
    int lane = tx & 31, warp = tx >> 5;
    int g = lane >> 2, tg = lane & 3;
    int vwarp = warp * 32;
    unsigned dynb = smem_u32(dyn);
    const char* wsrc = (const char*)g_Wsplit + (size_t)vt*NKC*WSTEP;
    const char* hsrc = (const char*)g_Hsplit;

    float acc[2][8][4];
    #pragma unroll
    for (int mi = 0; mi < 2; mi++)
        #pragma unroll
        for (int nb = 0; nb < 8; nb++)
            #pragma unroll
            for (int q = 0; q < 4; q++) acc[mi][nb][q] = 0.f;

    #define L_ISSUE(st_, buf_) do{                                             \
        unsigned db = dynb + (unsigned)(buf_)*STAGE;                           \
        const char* wsc = wsrc + (size_t)(st_)*WSTEP;                          \
        _Pragma("unroll")                                                      \
        for (int i_ = 0; i_ < 12; i_++){                                       \
            int idx = tx + i_*128;                                             \
            int rr = idx >> 2, kq = idx & 3;                                   \
            int sp = rr >> 7, vv = rr & 127;                                   \
            cp16(db + (unsigned)(sp*10240 + vv*PITCH + kq*16),                 \
                 wsc + (size_t)sp*8192 + vv*64 + kq*16);                       \
        }                                                                      \
        const char* hsc = hsrc + (size_t)(st_)*HSTEP;                          \
        _Pragma("unroll")                                                      \
        for (int i_ = 0; i_ < 6; i_++){                                        \
            int idx = tx + i_*128;                                             \
            int rr = idx >> 2, kq = idx & 3;                                   \
            int sp = rr >> 6, bb = rr & 63;                                    \
            cp16(db + (unsigned)(WREG + sp*5120 + bb*PITCH + kq*16),           \
                 hsc + (size_t)sp*4096 + bb*64 + kq*16);                       \
        }                                                                      \
    } while(0)

    L_ISSUE(0, 0); CP_COMMIT();
    L_ISSUE(1, 1); CP_COMMIT();

    for (int st = 0; st < NKC; st++){
        CP_WAIT1();
        __syncthreads();
        const char* sb = dyn + (st & 1)*STAGE;
        #pragma unroll
        for (int ks = 0; ks < 32; ks += 16){
            #pragma unroll
            for (int pa = 0; pa < 3; pa++){
                unsigned a[2][4];
                #pragma unroll
                for (int mi = 0; mi < 2; mi++){
                    int row = vwarp + mi*16 + g;
                    const char* ab = sb + pa*10240;
                    a[mi][0] = *(const unsigned*)(ab + (row    )*PITCH + (ks + 2*tg    )*2);
                    a[mi][1] = *(const unsigned*)(ab + (row + 8)*PITCH + (ks + 2*tg    )*2);
                    a[mi][2] = *(const unsigned*)(ab + (row    )*PITCH + (ks + 2*tg + 8)*2);
                    a[mi][3] = *(const unsigned*)(ab + (row + 8)*PITCH + (ks + 2*tg + 8)*2);
                }
                #pragma unroll
                for (int pb = 0; pb < 3; pb++){
                    if (pb >= 3 - pa) continue;   // products: i+j <= 2
                    const char* hb = sb + WREG + pb*5120;
                    unsigned bf[8][2];
                    #pragma unroll
                    for (int nb = 0; nb < 8; nb++){
                        int brow = nb*8 + g;
                        bf[nb][0] = *(const unsigned*)(hb + brow*PITCH + (ks + 2*tg    )*2);
                        bf[nb][1] = *(const unsigned*)(hb + brow*PITCH + (ks + 2*tg + 8)*2);
                    }
                    #pragma unroll
                    for (int mi = 0; mi < 2; mi++)
                        #pragma unroll
                        for (int nb = 0; nb < 8; nb++)
                            mma16816(acc[mi][nb], a[mi], bf[nb]);
                }
            }
        }
        __syncthreads();
        if (st + 2 < NKC) L_ISSUE(st + 2, st & 1);
        CP_COMMIT();
    }
    #undef L_ISSUE

    // -------- epilogue: stage D in smem [b][v], coalesced out + argmax --------
    asm volatile("cp.async.wait_group 0;");
    __syncthreads();
    float* sD = (float*)dyn;
    #pragma unroll
    for (int mi = 0; mi < 2; mi++)
        #pragma unroll
        for (int nb = 0; nb < 8; nb++){
            int v0 = vwarp + mi*16 + g;
            int b0 = nb*8 + 2*tg;
            sD[(b0    )*DPITCH + v0    ] = acc[mi][nb][0];
            sD[(b0 + 1)*DPITCH + v0    ] = acc[mi][nb][1];
            sD[(b0    )*DPITCH + v0 + 8] = acc[mi][nb][2];
            sD[(b0 + 1)*DPITCH + v0 + 8] = acc[mi][nb][3];
        }
    __syncthreads();

    int vblk = vt * 128;
    size_t tbase = (size_t)t * Bb * Vv;
    float* logits = out + 49152000ull;
    float4 zero4 = make_float4(0.f, 0.f, 0.f, 0.f);
    int v4 = lane * 4;
    float4 bo = *(const float4*)(b_out + vblk + v4);
    #pragma unroll
    for (int rr = 0; rr < 16; rr++){
        int b = rr*4 + warp;
        float4 d = *(const float4*)(sD + b*DPITCH + v4);
        d.x += bo.x; d.y += bo.y; d.z += bo.z; d.w += bo.w;
        size_t o = tbase + (size_t)b*Vv + vblk + v4;
        *(float4*)(logits + o) = d;
        *(float4*)(out + o) = zero4;
        // per-thread best over 4 (strictly-greater keeps lowest v on ties)
        float vals[4] = {d.x, d.y, d.z, d.w};
        unsigned bk = fkey(vals[0]); int bv = v4;
        #pragma unroll
        for (int q = 1; q < 4; q++){
            unsigned kq = fkey(vals[q]);
            if (kq > bk){ bk = kq; bv = v4 + q; }
        }
        unsigned m = __reduce_max_sync(0xFFFFFFFFu, bk);
        unsigned bal = __ballot_sync(0xFFFFFFFFu, bk == m);
        int src = __ffs(bal) - 1;
        if (lane == src){
            unsigned long long key = ((unsigned long long)m << 32) |
                (unsigned long long)(0xFFFFFFFFu - (unsigned)(vblk + bv));
            atomicMax(&g_amax[(size_t)t*Bb + b], key);
        }
    }
}

// -------- trailing finalize --------
__global__ void k_final(float* __restrict__ out){
    int b = threadIdx.x;
    if (b >= Bb) return;
    unsigned long long key = g_amax[(Tt-1)*Bb + b];
    int idx = dekey(key);
    out[(size_t)(Tt-1)*Bb*Vv + (size_t)b*Vv + idx] = 1.0f;
    out[98304000ull + (size_t)(Tt-1)*Bb + b] = g_mask[b];
}

extern "C" void kernel_launch(void* const* d_in, const int* in_sizes, int n_in,
                              void* d_out, int out_size){
    const float* eh    = (const float*)d_in[0];
    const float* ec    = (const float*)d_in[1];
    const float* W_ih  = (const float*)d_in[2];
    const float* W_hh  = (const float*)d_in[3];
    const float* b_ih  = (const float*)d_in[4];
    const float* b_hh  = (const float*)d_in[5];
    const float* W_out = (const float*)d_in[6];
    const float* b_out = (const float*)d_in[7];
    const float* x0    = (const float*)d_in[8];
    float* out = (float*)d_out;

    float* WhhT; cudaGetSymbolAddress((void**)&WhhT, g_WhhT);
    cudaFuncSetAttribute(k_logits_mma, cudaFuncAttributeMaxDynamicSharedMemorySize,
                         2*STAGE);

    k_init<<<128, 256>>>(eh, ec);
    k_wsplit<<<(Vv*Hh/8)/256, 256>>>(W_out);
    {   dim3 g(Gg/32, Hh/32), b(32, 8);
        k_transpose<<<g, b>>>(W_hh, WhhT, Gg, Hh); }
    k_zchk<<<8, 1024>>>(x0);
    k_xv<<<Gg, 256>>>(W_ih, x0);
    for (int t = 0; t < Tt; t++){
        k_gates<<<128, 256>>>(b_ih, b_hh, W_ih, out, t);
        k_logits_mma<<<NVT, 128, 2*STAGE>>>(b_out, out, t);
    }
    k_final<<<1, 64>>>(out);
}